// round 4
// baseline (speedup 1.0000x reference)
#include <cuda_runtime.h>

// out[b, 0, h, w] = 0.5f * (x[b,0,h,w] + x[b,1,h,w] + x[b,2,h,w])
// Exact algebraic collapse of the diagonal Haar decompose + reconstruct
// (see R0 derivation: every output pixel = 0.5 * channel-sum at same (h,w)).
//
// R4 (ceiling probe): 4 float4s per thread, block-strided -> 12 independent
// LDG.128 in flight per thread, L1-bypass loads (__ldcg, zero reuse),
// streaming stores. All warp accesses remain contiguous 512B lines.

static constexpr int B = 16;
static constexpr int C = 3;
static constexpr long long HW = 1024LL * 1024LL;            // elems per plane (2^20)
static constexpr long long OUT_ELEMS = (long long)B * HW;   // 16,777,216
static constexpr long long OUT_VECS = OUT_ELEMS / 4;        // 4,194,304 float4s
static constexpr int THREADS = 256;
static constexpr int VPT = 4;                               // float4s per thread
static constexpr long long VECS_PER_BLOCK = (long long)THREADS * VPT;   // 1024
static constexpr int GRID = (int)(OUT_VECS / VECS_PER_BLOCK);           // 4096
// Block chunk = 4096 elements; HW is a multiple of 4096, so a block never
// crosses a plane boundary.

__global__ void __launch_bounds__(THREADS) haar_chansum_kernel(
    const float* __restrict__ x, float* __restrict__ out) {
    long long v0 = (long long)blockIdx.x * VECS_PER_BLOCK + threadIdx.x;
    long long e0 = v0 * 4;                  // element index of thread's first float4
    long long b  = e0 >> 20;                // batch (HW = 2^20)
    long long p  = e0 & (HW - 1);           // pixel within plane
    const float* base = x + (b * C) * HW + p;

    const float4* c0 = reinterpret_cast<const float4*>(base);
    const float4* c1 = reinterpret_cast<const float4*>(base + HW);
    const float4* c2 = reinterpret_cast<const float4*>(base + 2LL * HW);

    // 12 independent, fully-coalesced, L1-bypassing LDG.128
    float4 a[VPT], bb[VPT], cc[VPT];
#pragma unroll
    for (int i = 0; i < VPT; i++) a[i]  = __ldcg(c0 + i * THREADS);
#pragma unroll
    for (int i = 0; i < VPT; i++) bb[i] = __ldcg(c1 + i * THREADS);
#pragma unroll
    for (int i = 0; i < VPT; i++) cc[i] = __ldcg(c2 + i * THREADS);

    float4* o = reinterpret_cast<float4*>(out + e0);
#pragma unroll
    for (int i = 0; i < VPT; i++) {
        float4 r;
        r.x = 0.5f * (a[i].x + bb[i].x + cc[i].x);
        r.y = 0.5f * (a[i].y + bb[i].y + cc[i].y);
        r.z = 0.5f * (a[i].z + bb[i].z + cc[i].z);
        r.w = 0.5f * (a[i].w + bb[i].w + cc[i].w);
        __stcs(o + i * THREADS, r);
    }
}

extern "C" void kernel_launch(void* const* d_in, const int* in_sizes, int n_in,
                              void* d_out, int out_size) {
    const float* x = (const float*)d_in[0];
    float* out = (float*)d_out;
    haar_chansum_kernel<<<GRID, THREADS>>>(x, out);
}

// round 5
// speedup vs baseline: 1.0142x; 1.0142x over previous
#include <cuda_runtime.h>

// out[b, 0, h, w] = 0.5f * (x[b,0,h,w] + x[b,1,h,w] + x[b,2,h,w])
// Exact algebraic collapse of the diagonal Haar decompose + reconstruct
// (see R0 derivation: every output pixel = 0.5 * channel-sum at same (h,w)).
//
// FINAL (= R3, measured optimum). Probes established a hard HBM floor at
// 36.832 us kernel time (268.4 MB / 7.29 TB/s effective, 91% of spec):
//   R1 (MLP=3, 16384x256)            36.832 us
//   R2 (MLP=6 adjacent-pair, ldcs)   36.832 us
//   R3 (MLP=6 block-strided)         36.832 us  <- this kernel
//   R4 (MLP=12, 1M threads, ldcg)    38.208 us  (lost chip-wide concurrency)
// 2 float4s per thread, block-strided so every warp LDG.128 is a contiguous
// 512B access; plain loads (zero reuse), streaming stores.

static constexpr int B = 16;
static constexpr int C = 3;
static constexpr long long HW = 1024LL * 1024LL;            // elems per plane (2^20)
static constexpr long long OUT_ELEMS = (long long)B * HW;   // 16,777,216
static constexpr long long OUT_VECS = OUT_ELEMS / 4;        // 4,194,304 float4s
static constexpr int THREADS = 512;
static constexpr int VPT = 2;                               // float4s per thread
static constexpr long long VECS_PER_BLOCK = (long long)THREADS * VPT;   // 1024
static constexpr int GRID = (int)(OUT_VECS / VECS_PER_BLOCK);           // 4096

__global__ void __launch_bounds__(THREADS) haar_chansum_kernel(
    const float* __restrict__ x, float* __restrict__ out) {
    // Thread handles vecs v0 and v0 + THREADS; the block's 1024-vec (4096-elem)
    // chunk never crosses a plane boundary (HW/4 = 262144 is a multiple of 1024).
    long long v0 = (long long)blockIdx.x * VECS_PER_BLOCK + threadIdx.x;
    long long e0 = v0 * 4;                  // element index of first float4
    long long b  = e0 >> 20;                // batch (HW = 2^20)
    long long p  = e0 & (HW - 1);           // pixel within plane
    const float* base = x + (b * C) * HW + p;

    const float4* c0 = reinterpret_cast<const float4*>(base);
    const float4* c1 = reinterpret_cast<const float4*>(base + HW);
    const float4* c2 = reinterpret_cast<const float4*>(base + 2LL * HW);

    // 6 independent, fully-coalesced LDG.128 (each warp access = 512B contiguous)
    float4 a0 = c0[0];
    float4 a1 = c1[0];
    float4 a2 = c2[0];
    float4 b0 = c0[THREADS];
    float4 b1 = c1[THREADS];
    float4 b2 = c2[THREADS];

    float4 r0, r1;
    r0.x = 0.5f * (a0.x + a1.x + a2.x);
    r0.y = 0.5f * (a0.y + a1.y + a2.y);
    r0.z = 0.5f * (a0.z + a1.z + a2.z);
    r0.w = 0.5f * (a0.w + a1.w + a2.w);
    r1.x = 0.5f * (b0.x + b1.x + b2.x);
    r1.y = 0.5f * (b0.y + b1.y + b2.y);
    r1.z = 0.5f * (b0.z + b1.z + b2.z);
    r1.w = 0.5f * (b0.w + b1.w + b2.w);

    float4* o = reinterpret_cast<float4*>(out + e0);
    __stcs(o + 0, r0);
    __stcs(o + THREADS, r1);
}

extern "C" void kernel_launch(void* const* d_in, const int* in_sizes, int n_in,
                              void* d_out, int out_size) {
    const float* x = (const float*)d_in[0];
    float* out = (float*)d_out;
    haar_chansum_kernel<<<GRID, THREADS>>>(x, out);
}

// round 6
// speedup vs baseline: 1.0384x; 1.0238x over previous
#include <cuda_runtime.h>
#include <cstdint>

// out[b, 0, h, w] = 0.5f * (x[b,0,h,w] + x[b,1,h,w] + x[b,2,h,w])
// Exact algebraic collapse of the diagonal Haar decompose + reconstruct
// (see R0 derivation: every output pixel = 0.5 * channel-sum at same (h,w)).
//
// R6: 256-bit global accesses (ld.global.nc.v8.b32 / st.global.cs.v8.b32,
// sm_100+). Same proven-optimal concurrency as R3/R5 (2M threads, 4096x512);
// each thread: 3x 32B loads (one per channel) + 1x 32B store. Warp accesses
// are contiguous 1024B. Measured floor so far: 36.19 us kernel, 7.42 TB/s.

static constexpr int B = 16;
static constexpr int C = 3;
static constexpr long long HW = 1024LL * 1024LL;            // elems per plane (2^20)
static constexpr long long OUT_ELEMS = (long long)B * HW;   // 16,777,216
static constexpr int EPT = 8;                               // elems per thread (one v8)
static constexpr long long N_THREADS = OUT_ELEMS / EPT;     // 2,097,152
static constexpr int THREADS = 512;
static constexpr int GRID = (int)(N_THREADS / THREADS);     // 4096

__device__ __forceinline__ void ldg256(const float* p, float* v) {
    uint32_t r0, r1, r2, r3, r4, r5, r6, r7;
    asm volatile(
        "ld.global.nc.v8.b32 {%0,%1,%2,%3,%4,%5,%6,%7}, [%8];"
        : "=r"(r0), "=r"(r1), "=r"(r2), "=r"(r3),
          "=r"(r4), "=r"(r5), "=r"(r6), "=r"(r7)
        : "l"(p));
    v[0] = __uint_as_float(r0); v[1] = __uint_as_float(r1);
    v[2] = __uint_as_float(r2); v[3] = __uint_as_float(r3);
    v[4] = __uint_as_float(r4); v[5] = __uint_as_float(r5);
    v[6] = __uint_as_float(r6); v[7] = __uint_as_float(r7);
}

__device__ __forceinline__ void stg256(float* p, const float* v) {
    asm volatile(
        "st.global.cs.v8.b32 [%0], {%1,%2,%3,%4,%5,%6,%7,%8};"
        :: "l"(p),
           "r"(__float_as_uint(v[0])), "r"(__float_as_uint(v[1])),
           "r"(__float_as_uint(v[2])), "r"(__float_as_uint(v[3])),
           "r"(__float_as_uint(v[4])), "r"(__float_as_uint(v[5])),
           "r"(__float_as_uint(v[6])), "r"(__float_as_uint(v[7]))
        : "memory");
}

__global__ void __launch_bounds__(THREADS) haar_chansum_kernel(
    const float* __restrict__ x, float* __restrict__ out) {
    long long t  = (long long)blockIdx.x * THREADS + threadIdx.x;
    long long e0 = t * EPT;                 // 8-elem (32B) aligned, within one plane
    long long b  = e0 >> 20;                // batch (HW = 2^20)
    long long p  = e0 & (HW - 1);           // pixel within plane
    const float* base = x + (b * C) * HW + p;

    float a0[8], a1[8], a2[8];
    ldg256(base,            a0);
    ldg256(base + HW,       a1);
    ldg256(base + 2LL * HW, a2);

    float r[8];
#pragma unroll
    for (int i = 0; i < 8; i++)
        r[i] = 0.5f * (a0[i] + a1[i] + a2[i]);

    stg256(out + e0, r);
}

extern "C" void kernel_launch(void* const* d_in, const int* in_sizes, int n_in,
                              void* d_out, int out_size) {
    const float* x = (const float*)d_in[0];
    float* out = (float*)d_out;
    haar_chansum_kernel<<<GRID, THREADS>>>(x, out);
}